// round 10
// baseline (speedup 1.0000x reference)
#include <cuda_runtime.h>
#include <cuda_bf16.h>
#include <math.h>

#define NN      20000
#define NE      320000
#define INDIM   128
#define HID     256
#define HEADS   8
#define DH      32
#define LAYERS  3
#define NG      64
#define OUTDIM  10
#define SLOPE   0.2f

#define K2IN  (INDIM / 2)
#define K2L   (HID / 2)
#define WIN_P (K2IN * HID)
#define WL_P  (K2L * HID)

// ---------------- scratch (device globals; no allocation allowed) ----------
__device__ float g_h[NN * HID];
__device__ float g_fs[NN * HID];
__device__ float g_fd[NN * HID];
__device__ unsigned g_ah_hi[NN * K2L];
__device__ unsigned g_ah_lo[NN * K2L];
__device__ unsigned g_af_hi[NN * K2IN];
__device__ unsigned g_af_lo[NN * K2IN];
__device__ unsigned g_win_hi[WIN_P], g_win_lo[WIN_P];
__device__ unsigned g_ws_hi[LAYERS * WL_P], g_ws_lo[LAYERS * WL_P];
__device__ unsigned g_wd_hi[LAYERS * WL_P], g_wd_lo[LAYERS * WL_P];
__device__ int g_cnt[NN];
__device__ int g_base[NN + 1];
__device__ int g_cur[NN];
__device__ int g_srcbyd[NE];
__device__ int g_gstart[NG + 1];

// ---------------- bf16 pack helpers -----------------------------------------
__device__ __forceinline__ unsigned pack_bf2(__nv_bfloat16 a, __nv_bfloat16 b) {
    return ((unsigned)__bfloat16_as_ushort(b) << 16) | (unsigned)__bfloat16_as_ushort(a);
}

__device__ __forceinline__ void split_pack(float x0, float x1, unsigned& hi, unsigned& lo) {
    __nv_bfloat16 h0 = __float2bfloat16_rn(x0);
    __nv_bfloat16 h1 = __float2bfloat16_rn(x1);
    __nv_bfloat16 l0 = __float2bfloat16_rn(x0 - __bfloat162float(h0));
    __nv_bfloat16 l1 = __float2bfloat16_rn(x1 - __bfloat162float(h1));
    hi = pack_bf2(h0, h1);
    lo = pack_bf2(l0, l1);
}

__device__ __forceinline__ void mma_bf16(float c[4], const unsigned a[4], const unsigned b[2]) {
    asm volatile(
        "mma.sync.aligned.m16n8k16.row.col.f32.bf16.bf16.f32 "
        "{%0,%1,%2,%3}, {%4,%5,%6,%7}, {%8,%9}, {%0,%1,%2,%3};"
        : "+f"(c[0]), "+f"(c[1]), "+f"(c[2]), "+f"(c[3])
        : "r"(a[0]), "r"(a[1]), "r"(a[2]), "r"(a[3]), "r"(b[0]), "r"(b[1]));
}

__device__ __forceinline__ void ldsm_x4(unsigned r[4], unsigned addr) {
    asm volatile("ldmatrix.sync.aligned.m8n8.x4.shared.b16 {%0,%1,%2,%3}, [%4];"
        : "=r"(r[0]), "=r"(r[1]), "=r"(r[2]), "=r"(r[3]) : "r"(addr));
}

// ---------------- pack everything in one launch -------------------------------
__global__ void pack_all_kernel(const float* __restrict__ W_in,
                                const float* __restrict__ W_src,
                                const float* __restrict__ W_dst,
                                const float* __restrict__ feature)
{
    int i = blockIdx.x * blockDim.x + threadIdx.x;
    const int NF = NN * K2IN;
    if (i < NF) {
        float2 v = ((const float2*)feature)[i];
        split_pack(v.x, v.y, g_af_hi[i], g_af_lo[i]);
        return;
    }
    int j = i - NF;
    if (j < WIN_P) {
        int k2 = j >> 8, n = j & 255;
        split_pack(W_in[(2 * k2) * HID + n], W_in[(2 * k2 + 1) * HID + n],
                   g_win_hi[j], g_win_lo[j]);
        return;
    }
    j -= WIN_P;
    if (j >= 2 * LAYERS * WL_P) return;
    int which = j / (LAYERS * WL_P);
    int rem = j - which * (LAYERS * WL_P);
    int l = rem / WL_P;
    int p = rem - l * WL_P;
    int k2 = p >> 8, n = p & 255;
    const float* W = (which ? W_dst : W_src) + (size_t)l * HID * HID;
    unsigned* hi = (which ? g_wd_hi : g_ws_hi) + (size_t)l * WL_P;
    unsigned* lo = (which ? g_wd_lo : g_ws_lo) + (size_t)l * WL_P;
    split_pack(W[(2 * k2) * HID + n], W[(2 * k2 + 1) * HID + n], hi[p], lo[p]);
}

// ---------------- bf16x3 mma.sync GEMM: 512 threads, warp tile 32x32 ----------
// C[M,256] = A[M,K]@B[K,256] + bias. A [row][K2] pairs; B [K2][256] pairs.
// grid.x in [0, 2*nb): nb N-tiles for C1, then nb for C2.
#define GBM 128
#define GBN 128
#define AST 20
#define BST 136
#define OFF_ALO 20480
#define OFF_BHI 40960
#define OFF_BLO 58368
#define GSMEM   75776

__global__ __launch_bounds__(512) void gemm_bf16x3_kernel(
    const unsigned* __restrict__ Ahi, const unsigned* __restrict__ Alo,
    const unsigned* __restrict__ B1hi, const unsigned* __restrict__ B1lo,
    const unsigned* __restrict__ B2hi, const unsigned* __restrict__ B2lo,
    const float* __restrict__ bias1, const float* __restrict__ bias2,
    float* __restrict__ C1, float* __restrict__ C2,
    unsigned* __restrict__ Pho, unsigned* __restrict__ Plo,
    int M, int K2g, int nb, int do_pack)
{
    extern __shared__ __align__(16) unsigned char dsm[];
    unsigned* As_hi = (unsigned*)dsm;                    // [2][128][20]
    unsigned* As_lo = (unsigned*)(dsm + OFF_ALO);
    unsigned* Bs_hi = (unsigned*)(dsm + OFF_BHI);        // [2][16][136]
    unsigned* Bs_lo = (unsigned*)(dsm + OFF_BLO);

    int bx = blockIdx.x;
    int which = 0;
    if (bx >= nb) { which = 1; bx -= nb; }
    const unsigned* Bhi = which ? B2hi : B1hi;
    const unsigned* Blo = which ? B2lo : B1lo;
    const float* bias   = which ? bias2 : bias1;
    float* C            = which ? C2 : C1;

    const int tid  = threadIdx.x;
    const int wid  = tid >> 5;              // 0..15
    const int lane = tid & 31;
    const int wm   = (wid >> 2) * 32;       // 0,32,64,96
    const int wn   = (wid & 3) * 32;        // 0,32,64,96
    const int grp  = lane >> 2;
    const int tig  = lane & 3;
    const int row0 = blockIdx.y * GBM;
    const int col0 = bx * GBN;

    // loaders: 512 threads, exactly 1 uint4 per thread per array per stage
    const int arw = tid >> 2;               // A row 0..127
    const int asg = (tid & 3) * 4;          // A pair col 0,4,8,12
    const int brw = tid >> 5;               // B row 0..15
    const int bcc = (tid & 31) * 4;         // B col

    const int lrow = wm + (lane & 15);
    const int lcol = (lane >> 4) * 4;
    const unsigned sa_hi = (unsigned)__cvta_generic_to_shared(As_hi);
    const unsigned sa_lo = (unsigned)__cvta_generic_to_shared(As_lo);

    float c[2][4][4];
    #pragma unroll
    for (int i = 0; i < 2; i++)
        #pragma unroll
        for (int j = 0; j < 4; j++)
            #pragma unroll
            for (int k = 0; k < 4; k++) c[i][j][k] = 0.f;

    uint4 vah, val2, vbh, vbl;

    #define LD_REGS(t) do {                                                    \
        int kb = (t) * 16;                                                     \
        bool ok = (row0 + arw) < M;                                            \
        size_t go = (size_t)(row0 + arw) * K2g + kb + asg;                     \
        vah = make_uint4(0,0,0,0); val2 = vah;                                 \
        if (ok) { vah = *(const uint4*)(Ahi + go);                             \
                  val2 = *(const uint4*)(Alo + go); }                          \
        size_t gb = (size_t)(kb + brw) * 256 + col0 + bcc;                     \
        vbh = *(const uint4*)(Bhi + gb);                                       \
        vbl = *(const uint4*)(Blo + gb);                                       \
    } while (0)

    #define ST_SMEM(s) do {                                                   \
        int ai = ((s) * 128 + arw) * AST + asg;                               \
        *(uint4*)(As_hi + ai) = vah;                                          \
        *(uint4*)(As_lo + ai) = val2;                                         \
        int bi = ((s) * 16 + brw) * BST + bcc;                                \
        *(uint4*)(Bs_hi + bi) = vbh;                                          \
        *(uint4*)(Bs_lo + bi) = vbl;                                          \
    } while (0)

    LD_REGS(0);
    ST_SMEM(0);
    __syncthreads();

    const int nk = K2g >> 4;   // chunks of 16 pairs (32 k)
    for (int t = 0; t < nk; t++) {
        const int cb = t & 1;
        const bool more = (t + 1 < nk);
        if (more) LD_REGS(t + 1);

        #pragma unroll
        for (int kk = 0; kk < 2; kk++) {
            unsigned ah[2][4], al[2][4], bh[4][2], bl[4][2];
            #pragma unroll
            for (int mt = 0; mt < 2; mt++) {
                unsigned off = (((unsigned)(cb * GBM + lrow + mt * 16)) * AST
                                + kk * 8 + lcol) * 4u;
                ldsm_x4(ah[mt], sa_hi + off);
                ldsm_x4(al[mt], sa_lo + off);
            }
            #pragma unroll
            for (int nt = 0; nt < 4; nt++) {
                int cn = wn + nt * 8 + grp;
                int r0 = (cb * 16 + kk * 8 + tig) * BST;
                bh[nt][0] = Bs_hi[r0 + cn];      bh[nt][1] = Bs_hi[r0 + 4 * BST + cn];
                bl[nt][0] = Bs_lo[r0 + cn];      bl[nt][1] = Bs_lo[r0 + 4 * BST + cn];
            }
            #pragma unroll
            for (int mt = 0; mt < 2; mt++)
                #pragma unroll
                for (int nt = 0; nt < 4; nt++) {
                    mma_bf16(c[mt][nt], ah[mt], bl[nt]);
                    mma_bf16(c[mt][nt], al[mt], bh[nt]);
                    mma_bf16(c[mt][nt], ah[mt], bh[nt]);
                }
        }

        if (more) {
            __syncthreads();
            ST_SMEM(1 - cb);
            __syncthreads();
        }
    }

    #pragma unroll
    for (int nt = 0; nt < 4; nt++) {
        int cc = col0 + wn + nt * 8 + 2 * tig;
        float b0 = bias[cc], b1 = bias[cc + 1];
        #pragma unroll
        for (int mt = 0; mt < 2; mt++) {
            int r0 = row0 + wm + mt * 16 + grp;
            if (r0 < M) {
                float v0 = c[mt][nt][0] + b0, v1 = c[mt][nt][1] + b1;
                *(float2*)(C + (size_t)r0 * HID + cc) = make_float2(v0, v1);
                if (do_pack && which == 0) {
                    unsigned hi, lo;
                    split_pack(v0, v1, hi, lo);
                    size_t pi = ((size_t)r0 * HID + cc) >> 1;
                    Pho[pi] = hi; Plo[pi] = lo;
                }
            }
            int r1 = r0 + 8;
            if (r1 < M) {
                float v0 = c[mt][nt][2] + b0, v1 = c[mt][nt][3] + b1;
                *(float2*)(C + (size_t)r1 * HID + cc) = make_float2(v0, v1);
                if (do_pack && which == 0) {
                    unsigned hi, lo;
                    split_pack(v0, v1, hi, lo);
                    size_t pi = ((size_t)r1 * HID + cc) >> 1;
                    Pho[pi] = hi; Plo[pi] = lo;
                }
            }
        }
    }
    #undef LD_REGS
    #undef ST_SMEM
}

// ---------------- CSR build (second stream) ----------------------------------
__global__ void zero_cnt_kernel() {
    int i = blockIdx.x * blockDim.x + threadIdx.x;
    if (i < NN) g_cnt[i] = 0;
}

__global__ void count_kernel(const int* __restrict__ dst) {
    int e = blockIdx.x * blockDim.x + threadIdx.x;
    if (e < NE) atomicAdd(&g_cnt[dst[e]], 1);
}

__global__ __launch_bounds__(1024) void scan_kernel() {
    __shared__ int s[1024];
    int t = threadIdx.x;
    int lo = t * 20;
    int hi = lo + 20; if (hi > NN) hi = NN;
    int sum = 0;
    for (int i = lo; i < hi; i++) sum += g_cnt[i];
    s[t] = sum;
    __syncthreads();
    for (int off = 1; off < 1024; off <<= 1) {
        int v = (t >= off) ? s[t - off] : 0;
        __syncthreads();
        s[t] += v;
        __syncthreads();
    }
    int run = s[t] - sum;
    for (int i = lo; i < hi; i++) {
        g_base[i] = run;
        g_cur[i] = run;
        run += g_cnt[i];
    }
    if (t == 0) g_base[NN] = NE;
}

__global__ void fill_kernel(const int* __restrict__ src, const int* __restrict__ dst) {
    int e = blockIdx.x * blockDim.x + threadIdx.x;
    if (e < NE) {
        int p = atomicAdd(&g_cur[dst[e]], 1);
        g_srcbyd[p] = src[e];
    }
}

__global__ void gbound_kernel(const int* __restrict__ gids) {
    int g = threadIdx.x;
    if (g > NG) return;
    int lo = 0, hi = NN;
    while (lo < hi) {
        int mid = (lo + hi) >> 1;
        if (gids[mid] < g) lo = mid + 1; else hi = mid;
    }
    g_gstart[g] = lo;
}

// ------- fused edge kernel: one warp per NODE, all 8 heads at once -----------
__global__ __launch_bounds__(256) void fused_edge_kernel(const float* __restrict__ attn,
                                                         int do_pack)
{
    int n = blockIdx.x * 8 + (threadIdx.x >> 5);
    int lane = threadIdx.x & 31;
    if (n >= NN) return;
    const size_t rowoff = (size_t)n * HID + lane * 8;

    float fdv[8], av[8];
    {
        float4 t0 = *(const float4*)(g_fd + rowoff);
        float4 t1 = *(const float4*)(g_fd + rowoff + 4);
        fdv[0]=t0.x; fdv[1]=t0.y; fdv[2]=t0.z; fdv[3]=t0.w;
        fdv[4]=t1.x; fdv[5]=t1.y; fdv[6]=t1.z; fdv[7]=t1.w;
        float4 a0 = *(const float4*)(attn + lane * 8);
        float4 a1 = *(const float4*)(attn + lane * 8 + 4);
        av[0]=a0.x; av[1]=a0.y; av[2]=a0.z; av[3]=a0.w;
        av[4]=a1.x; av[5]=a1.y; av[6]=a1.z; av[7]=a1.w;
    }

    const int b  = g_base[n];
    const int e2 = g_base[n + 1];

    float m = -1e30f, sd = 0.f;
    float acc[8] = {0.f,0.f,0.f,0.f,0.f,0.f,0.f,0.f};

    for (int j = b; j < e2; j++) {
        int s = g_srcbyd[j];
        const float4* fp = (const float4*)(g_fs + (size_t)s * HID + lane * 8);
        float4 a0 = fp[0], a1 = fp[1];
        float fsv[8] = {a0.x,a0.y,a0.z,a0.w,a1.x,a1.y,a1.z,a1.w};
        float pp = 0.f;
        #pragma unroll
        for (int q = 0; q < 8; q++) {
            float v = fsv[q] + fdv[q];
            v = (v > 0.f) ? v : SLOPE * v;
            pp = fmaf(v, av[q], pp);
        }
        pp += __shfl_xor_sync(0xffffffffu, pp, 1);
        pp += __shfl_xor_sync(0xffffffffu, pp, 2);
        float nm = fmaxf(m, pp);
        float fac = __expf(m - nm);
        float w   = __expf(pp - nm);
        sd = sd * fac + w;
        #pragma unroll
        for (int q = 0; q < 8; q++) acc[q] = fmaf(acc[q], fac, w * fsv[q]);
        m = nm;
    }

    float inv = (sd > 0.f) ? 1.f / sd : 0.f;
    float hv[8];
    {
        float4 h0 = *(const float4*)(g_h + rowoff);
        float4 h1 = *(const float4*)(g_h + rowoff + 4);
        float hold[8] = {h0.x,h0.y,h0.z,h0.w,h1.x,h1.y,h1.z,h1.w};
        #pragma unroll
        for (int q = 0; q < 8; q++) hv[q] = fmaxf(fmaf(acc[q], inv, hold[q]), 0.f);
    }
    *(float4*)(g_h + rowoff)     = make_float4(hv[0], hv[1], hv[2], hv[3]);
    *(float4*)(g_h + rowoff + 4) = make_float4(hv[4], hv[5], hv[6], hv[7]);
    if (do_pack) {
        size_t pbase = rowoff >> 1;
        #pragma unroll
        for (int q = 0; q < 8; q += 2) {
            unsigned hi, lo;
            split_pack(hv[q], hv[q + 1], hi, lo);
            g_ah_hi[pbase + (q >> 1)] = hi;
            g_ah_lo[pbase + (q >> 1)] = lo;
        }
    }
}

// ---------------- fused pool + 3-layer classifier, one block per graph -------
__global__ __launch_bounds__(256) void poolfc_kernel(
    const float* __restrict__ Wc1, const float* __restrict__ bc1,
    const float* __restrict__ Wc2, const float* __restrict__ bc2,
    const float* __restrict__ Wc3, const float* __restrict__ bc3,
    float* __restrict__ out)
{
    __shared__ float sh[256];
    __shared__ float sx[256];
    int g = blockIdx.x;
    int c = threadIdx.x;
    int n0 = g_gstart[g], n1 = g_gstart[g + 1];
    float s = 0.f;
    for (int n = n0; n < n1; n++) s += g_h[(size_t)n * HID + c];
    sh[c] = s;
    __syncthreads();
    float a = bc1[c];
    #pragma unroll 8
    for (int k = 0; k < HID; k++) a = fmaf(sh[k], Wc1[k * HID + c], a);
    sx[c] = fmaxf(a, 0.f);
    __syncthreads();
    float b2 = 0.f;
    if (c < HID / 2) {
        b2 = bc2[c];
        #pragma unroll 8
        for (int k = 0; k < HID; k++) b2 = fmaf(sx[k], Wc2[k * (HID / 2) + c], b2);
        b2 = fmaxf(b2, 0.f);
    }
    __syncthreads();
    if (c < HID / 2) sh[c] = b2;
    __syncthreads();
    if (c < OUTDIM) {
        float o = bc3[c];
        for (int k = 0; k < HID / 2; k++) o = fmaf(sh[k], Wc3[k * OUTDIM + c], o);
        out[g * OUTDIM + c] = o;
    }
}

// ---------------- launch -------------------------------------------------------
extern "C" void kernel_launch(void* const* d_in, const int* in_sizes, int n_in,
                              void* d_out, int out_size)
{
    const float* feature   = (const float*)d_in[0];
    const float* W_in      = (const float*)d_in[1];
    const float* b_in      = (const float*)d_in[2];
    const float* W_src     = (const float*)d_in[3];
    const float* b_src     = (const float*)d_in[4];
    const float* W_dst     = (const float*)d_in[5];
    const float* b_dst     = (const float*)d_in[6];
    const float* attn      = (const float*)d_in[7];
    const float* Wc1       = (const float*)d_in[8];
    const float* bc1       = (const float*)d_in[9];
    const float* Wc2       = (const float*)d_in[10];
    const float* bc2       = (const float*)d_in[11];
    const float* Wc3       = (const float*)d_in[12];
    const float* bc3       = (const float*)d_in[13];
    const int*   src       = (const int*)d_in[14];
    const int*   dst       = (const int*)d_in[15];
    const int*   graph_ids = (const int*)d_in[16];
    float* out = (float*)d_out;

    float *p_h, *p_fs, *p_fd;
    unsigned *p_ah_hi, *p_ah_lo, *p_af_hi, *p_af_lo;
    unsigned *p_win_hi, *p_win_lo, *p_ws_hi, *p_ws_lo, *p_wd_hi, *p_wd_lo;
    cudaGetSymbolAddress((void**)&p_h,  g_h);
    cudaGetSymbolAddress((void**)&p_fs, g_fs);
    cudaGetSymbolAddress((void**)&p_fd, g_fd);
    cudaGetSymbolAddress((void**)&p_ah_hi, g_ah_hi);
    cudaGetSymbolAddress((void**)&p_ah_lo, g_ah_lo);
    cudaGetSymbolAddress((void**)&p_af_hi, g_af_hi);
    cudaGetSymbolAddress((void**)&p_af_lo, g_af_lo);
    cudaGetSymbolAddress((void**)&p_win_hi, g_win_hi);
    cudaGetSymbolAddress((void**)&p_win_lo, g_win_lo);
    cudaGetSymbolAddress((void**)&p_ws_hi, g_ws_hi);
    cudaGetSymbolAddress((void**)&p_ws_lo, g_ws_lo);
    cudaGetSymbolAddress((void**)&p_wd_hi, g_wd_hi);
    cudaGetSymbolAddress((void**)&p_wd_lo, g_wd_lo);

    cudaFuncSetAttribute(gemm_bf16x3_kernel,
                         cudaFuncAttributeMaxDynamicSharedMemorySize, GSMEM);

    // fork: CSR chain on a second stream, overlapped with pack + GEMM1
    cudaStream_t s2;
    cudaStreamCreateWithFlags(&s2, cudaStreamNonBlocking);
    cudaEvent_t evA, evB;
    cudaEventCreateWithFlags(&evA, cudaEventDisableTiming);
    cudaEventCreateWithFlags(&evB, cudaEventDisableTiming);
    cudaEventRecord(evA, 0);
    cudaStreamWaitEvent(s2, evA, 0);
    zero_cnt_kernel<<<(NN + 255) / 256, 256, 0, s2>>>();
    count_kernel<<<(NE + 255) / 256, 256, 0, s2>>>(dst);
    scan_kernel<<<1, 1024, 0, s2>>>();
    fill_kernel<<<(NE + 255) / 256, 256, 0, s2>>>(src, dst);
    gbound_kernel<<<1, 128, 0, s2>>>(graph_ids);
    cudaEventRecord(evB, s2);

    // main stream: pack, GEMM1
    const int NPACK = NN * K2IN + WIN_P + 2 * LAYERS * WL_P;
    pack_all_kernel<<<(NPACK + 255) / 256, 256>>>(W_in, W_src, W_dst, feature);

    const int MROWS = (NN + GBM - 1) / GBM;
    const int NB = HID / GBN;          // 2 N-tiles per output
    dim3 grid1(NB, MROWS);
    dim3 grid2(2 * NB, MROWS);

    gemm_bf16x3_kernel<<<grid1, 512, GSMEM>>>(
        p_af_hi, p_af_lo, p_win_hi, p_win_lo, p_win_hi, p_win_lo,
        b_in, b_in, p_h, p_h, p_ah_hi, p_ah_lo,
        NN, K2IN, NB, 1);

    cudaStreamWaitEvent(0, evB, 0);

    const int fused_blocks = (NN + 7) / 8;
    for (int l = 0; l < LAYERS; l++) {
        const float* bs = b_src + (size_t)l * HID;
        const float* bd = b_dst + (size_t)l * HID;
        const float* al = attn + (size_t)l * HEADS * DH;

        gemm_bf16x3_kernel<<<grid2, 512, GSMEM>>>(
            p_ah_hi, p_ah_lo,
            p_ws_hi + (size_t)l * WL_P, p_ws_lo + (size_t)l * WL_P,
            p_wd_hi + (size_t)l * WL_P, p_wd_lo + (size_t)l * WL_P,
            bs, bd, p_fs, p_fd, (unsigned*)0, (unsigned*)0,
            NN, K2L, NB, 0);

        fused_edge_kernel<<<fused_blocks, 256>>>(al, (l + 1 < LAYERS) ? 1 : 0);
    }

    poolfc_kernel<<<NG, 256>>>(Wc1, bc1, Wc2, bc2, Wc3, bc3, out);
}

// round 11
// speedup vs baseline: 1.0804x; 1.0804x over previous
#include <cuda_runtime.h>
#include <cuda_bf16.h>
#include <math.h>

#define NN      20000
#define NE      320000
#define INDIM   128
#define HID     256
#define HEADS   8
#define DH      32
#define LAYERS  3
#define NG      64
#define OUTDIM  10
#define SLOPE   0.2f

#define K2IN  (INDIM / 2)
#define K2L   (HID / 2)
#define WIN_P (K2IN * HID)
#define WL_P  (K2L * HID)

// ---------------- scratch (device globals; no allocation allowed) ----------
__device__ float g_h[NN * HID];
__device__ float g_fs[NN * HID];
__device__ float g_fd[NN * HID];
__device__ unsigned g_ah_hi[NN * K2L];
__device__ unsigned g_ah_lo[NN * K2L];
__device__ unsigned g_af_hi[NN * K2IN];
__device__ unsigned g_af_lo[NN * K2IN];
__device__ unsigned g_win_hi[WIN_P], g_win_lo[WIN_P];
__device__ unsigned g_ws_hi[LAYERS * WL_P], g_ws_lo[LAYERS * WL_P];
__device__ unsigned g_wd_hi[LAYERS * WL_P], g_wd_lo[LAYERS * WL_P];
__device__ int g_cnt[NN];
__device__ int g_base[NN + 1];
__device__ int g_cur[NN];
__device__ int g_srcbyd[NE];
__device__ int g_gstart[NG + 1];

// ---------------- bf16 pack helpers -----------------------------------------
__device__ __forceinline__ unsigned pack_bf2(__nv_bfloat16 a, __nv_bfloat16 b) {
    return ((unsigned)__bfloat16_as_ushort(b) << 16) | (unsigned)__bfloat16_as_ushort(a);
}

__device__ __forceinline__ void split_pack(float x0, float x1, unsigned& hi, unsigned& lo) {
    __nv_bfloat16 h0 = __float2bfloat16_rn(x0);
    __nv_bfloat16 h1 = __float2bfloat16_rn(x1);
    __nv_bfloat16 l0 = __float2bfloat16_rn(x0 - __bfloat162float(h0));
    __nv_bfloat16 l1 = __float2bfloat16_rn(x1 - __bfloat162float(h1));
    hi = pack_bf2(h0, h1);
    lo = pack_bf2(l0, l1);
}

__device__ __forceinline__ void mma_bf16(float c[4], const unsigned a[4], const unsigned b[2]) {
    asm volatile(
        "mma.sync.aligned.m16n8k16.row.col.f32.bf16.bf16.f32 "
        "{%0,%1,%2,%3}, {%4,%5,%6,%7}, {%8,%9}, {%0,%1,%2,%3};"
        : "+f"(c[0]), "+f"(c[1]), "+f"(c[2]), "+f"(c[3])
        : "r"(a[0]), "r"(a[1]), "r"(a[2]), "r"(a[3]), "r"(b[0]), "r"(b[1]));
}

__device__ __forceinline__ void ldsm_x4(unsigned r[4], unsigned addr) {
    asm volatile("ldmatrix.sync.aligned.m8n8.x4.shared.b16 {%0,%1,%2,%3}, [%4];"
        : "=r"(r[0]), "=r"(r[1]), "=r"(r[2]), "=r"(r[3]) : "r"(addr));
}

// ---------------- pack everything in one launch -------------------------------
__global__ void pack_all_kernel(const float* __restrict__ W_in,
                                const float* __restrict__ W_src,
                                const float* __restrict__ W_dst,
                                const float* __restrict__ feature)
{
    int i = blockIdx.x * blockDim.x + threadIdx.x;
    const int NF = NN * K2IN;
    if (i < NF) {
        float2 v = ((const float2*)feature)[i];
        split_pack(v.x, v.y, g_af_hi[i], g_af_lo[i]);
        return;
    }
    int j = i - NF;
    if (j < WIN_P) {
        int k2 = j >> 8, n = j & 255;
        split_pack(W_in[(2 * k2) * HID + n], W_in[(2 * k2 + 1) * HID + n],
                   g_win_hi[j], g_win_lo[j]);
        return;
    }
    j -= WIN_P;
    if (j >= 2 * LAYERS * WL_P) return;
    int which = j / (LAYERS * WL_P);
    int rem = j - which * (LAYERS * WL_P);
    int l = rem / WL_P;
    int p = rem - l * WL_P;
    int k2 = p >> 8, n = p & 255;
    const float* W = (which ? W_dst : W_src) + (size_t)l * HID * HID;
    unsigned* hi = (which ? g_wd_hi : g_ws_hi) + (size_t)l * WL_P;
    unsigned* lo = (which ? g_wd_lo : g_ws_lo) + (size_t)l * WL_P;
    split_pack(W[(2 * k2) * HID + n], W[(2 * k2 + 1) * HID + n], hi[p], lo[p]);
}

// ---------------- bf16x3 mma.sync GEMM: 64x128 tile, 256 thr, 2 CTAs/SM ------
// C[M,256] = A[M,K]@B[K,256] + bias. A [row][K2] pairs; B [K2][256] pairs.
// grid.x in [0, 2*nb): nb N-tiles for C1, then nb for C2.
#define GBM 64
#define GBN 128
#define AST 20
#define BST 136
// dynamic smem u32/byte offsets: As 2*64*20*4 = 10240 B per array
#define OFF_ALO 10240
#define OFF_BHI 20480
#define OFF_BLO 37888             // + 2*16*136*4 = 17408
#define GSMEM   55296

__global__ __launch_bounds__(256) void gemm_bf16x3_kernel(
    const unsigned* __restrict__ Ahi, const unsigned* __restrict__ Alo,
    const unsigned* __restrict__ B1hi, const unsigned* __restrict__ B1lo,
    const unsigned* __restrict__ B2hi, const unsigned* __restrict__ B2lo,
    const float* __restrict__ bias1, const float* __restrict__ bias2,
    float* __restrict__ C1, float* __restrict__ C2,
    unsigned* __restrict__ Pho, unsigned* __restrict__ Plo,
    int M, int K2g, int nb, int do_pack)
{
    extern __shared__ __align__(16) unsigned char dsm[];
    unsigned* As_hi = (unsigned*)dsm;                    // [2][64][20]
    unsigned* As_lo = (unsigned*)(dsm + OFF_ALO);
    unsigned* Bs_hi = (unsigned*)(dsm + OFF_BHI);        // [2][16][136]
    unsigned* Bs_lo = (unsigned*)(dsm + OFF_BLO);

    int bx = blockIdx.x;
    int which = 0;
    if (bx >= nb) { which = 1; bx -= nb; }
    const unsigned* Bhi = which ? B2hi : B1hi;
    const unsigned* Blo = which ? B2lo : B1lo;
    const float* bias   = which ? bias2 : bias1;
    float* C            = which ? C2 : C1;

    const int tid  = threadIdx.x;
    const int wid  = tid >> 5;              // 0..7
    const int lane = tid & 31;
    const int wm   = (wid >> 2) * 32;       // 0,32
    const int wn   = (wid & 3) * 32;        // 0..96
    const int grp  = lane >> 2;
    const int tig  = lane & 3;
    const int row0 = blockIdx.y * GBM;
    const int col0 = bx * GBN;

    // loaders: A 64x16 pairs = 256 uint4 (1/thread); B 16x128 = 512 uint4 (2/thread)
    const int arw = tid >> 2;               // A row 0..63
    const int asg = (tid & 3) * 4;          // A pair col 0,4,8,12
    const int brw = tid >> 5;               // B row 0..7 (+8)
    const int bcc = (tid & 31) * 4;         // B col

    const int lrow = wm + (lane & 15);
    const int lcol = (lane >> 4) * 4;
    const unsigned sa_hi = (unsigned)__cvta_generic_to_shared(As_hi);
    const unsigned sa_lo = (unsigned)__cvta_generic_to_shared(As_lo);

    float c[2][4][4];
    #pragma unroll
    for (int i = 0; i < 2; i++)
        #pragma unroll
        for (int j = 0; j < 4; j++)
            #pragma unroll
            for (int k = 0; k < 4; k++) c[i][j][k] = 0.f;

    uint4 vah, val2, vbh[2], vbl[2];

    #define LD_REGS(t) do {                                                    \
        int kb = (t) * 16;                                                     \
        bool ok = (row0 + arw) < M;                                            \
        size_t go = (size_t)(row0 + arw) * K2g + kb + asg;                     \
        vah = make_uint4(0,0,0,0); val2 = vah;                                 \
        if (ok) { vah = *(const uint4*)(Ahi + go);                             \
                  val2 = *(const uint4*)(Alo + go); }                          \
        _Pragma("unroll")                                                      \
        for (int i = 0; i < 2; i++) {                                          \
            size_t gb = (size_t)(kb + brw + i * 8) * 256 + col0 + bcc;         \
            vbh[i] = *(const uint4*)(Bhi + gb);                                \
            vbl[i] = *(const uint4*)(Blo + gb);                                \
        }                                                                      \
    } while (0)

    #define ST_SMEM(s) do {                                                   \
        int ai = ((s) * GBM + arw) * AST + asg;                               \
        *(uint4*)(As_hi + ai) = vah;                                          \
        *(uint4*)(As_lo + ai) = val2;                                         \
        _Pragma("unroll")                                                      \
        for (int i = 0; i < 2; i++) {                                         \
            int bi = ((s) * 16 + brw + i * 8) * BST + bcc;                    \
            *(uint4*)(Bs_hi + bi) = vbh[i];                                   \
            *(uint4*)(Bs_lo + bi) = vbl[i];                                   \
        }                                                                     \
    } while (0)

    LD_REGS(0);
    ST_SMEM(0);
    __syncthreads();

    const int nk = K2g >> 4;   // chunks of 16 pairs (32 k)
    for (int t = 0; t < nk; t++) {
        const int cb = t & 1;
        const bool more = (t + 1 < nk);
        if (more) LD_REGS(t + 1);

        #pragma unroll
        for (int kk = 0; kk < 2; kk++) {
            unsigned ah[2][4], al[2][4], bh[4][2], bl[4][2];
            #pragma unroll
            for (int mt = 0; mt < 2; mt++) {
                unsigned off = (((unsigned)(cb * GBM + lrow + mt * 16)) * AST
                                + kk * 8 + lcol) * 4u;
                ldsm_x4(ah[mt], sa_hi + off);
                ldsm_x4(al[mt], sa_lo + off);
            }
            #pragma unroll
            for (int nt = 0; nt < 4; nt++) {
                int cn = wn + nt * 8 + grp;
                int r0 = (cb * 16 + kk * 8 + tig) * BST;
                bh[nt][0] = Bs_hi[r0 + cn];      bh[nt][1] = Bs_hi[r0 + 4 * BST + cn];
                bl[nt][0] = Bs_lo[r0 + cn];      bl[nt][1] = Bs_lo[r0 + 4 * BST + cn];
            }
            #pragma unroll
            for (int mt = 0; mt < 2; mt++)
                #pragma unroll
                for (int nt = 0; nt < 4; nt++) {
                    mma_bf16(c[mt][nt], ah[mt], bl[nt]);
                    mma_bf16(c[mt][nt], al[mt], bh[nt]);
                    mma_bf16(c[mt][nt], ah[mt], bh[nt]);
                }
        }

        if (more) {
            __syncthreads();
            ST_SMEM(1 - cb);
            __syncthreads();
        }
    }

    #pragma unroll
    for (int nt = 0; nt < 4; nt++) {
        int cc = col0 + wn + nt * 8 + 2 * tig;
        float b0 = bias[cc], b1 = bias[cc + 1];
        #pragma unroll
        for (int mt = 0; mt < 2; mt++) {
            int r0 = row0 + wm + mt * 16 + grp;
            if (r0 < M) {
                float v0 = c[mt][nt][0] + b0, v1 = c[mt][nt][1] + b1;
                *(float2*)(C + (size_t)r0 * HID + cc) = make_float2(v0, v1);
                if (do_pack && which == 0) {
                    unsigned hi, lo;
                    split_pack(v0, v1, hi, lo);
                    size_t pi = ((size_t)r0 * HID + cc) >> 1;
                    Pho[pi] = hi; Plo[pi] = lo;
                }
            }
            int r1 = r0 + 8;
            if (r1 < M) {
                float v0 = c[mt][nt][2] + b0, v1 = c[mt][nt][3] + b1;
                *(float2*)(C + (size_t)r1 * HID + cc) = make_float2(v0, v1);
                if (do_pack && which == 0) {
                    unsigned hi, lo;
                    split_pack(v0, v1, hi, lo);
                    size_t pi = ((size_t)r1 * HID + cc) >> 1;
                    Pho[pi] = hi; Plo[pi] = lo;
                }
            }
        }
    }
    #undef LD_REGS
    #undef ST_SMEM
}

// ---------------- CSR build (second stream) ----------------------------------
__global__ void zero_cnt_kernel() {
    int i = blockIdx.x * blockDim.x + threadIdx.x;
    if (i < NN) g_cnt[i] = 0;
}

__global__ void count_kernel(const int* __restrict__ dst) {
    int e = blockIdx.x * blockDim.x + threadIdx.x;
    if (e < NE) atomicAdd(&g_cnt[dst[e]], 1);
}

__global__ __launch_bounds__(1024) void scan_kernel() {
    __shared__ int s[1024];
    int t = threadIdx.x;
    int lo = t * 20;
    int hi = lo + 20; if (hi > NN) hi = NN;
    int sum = 0;
    for (int i = lo; i < hi; i++) sum += g_cnt[i];
    s[t] = sum;
    __syncthreads();
    for (int off = 1; off < 1024; off <<= 1) {
        int v = (t >= off) ? s[t - off] : 0;
        __syncthreads();
        s[t] += v;
        __syncthreads();
    }
    int run = s[t] - sum;
    for (int i = lo; i < hi; i++) {
        g_base[i] = run;
        g_cur[i] = run;
        run += g_cnt[i];
    }
    if (t == 0) g_base[NN] = NE;
}

__global__ void fill_kernel(const int* __restrict__ src, const int* __restrict__ dst) {
    int e = blockIdx.x * blockDim.x + threadIdx.x;
    if (e < NE) {
        int p = atomicAdd(&g_cur[dst[e]], 1);
        g_srcbyd[p] = src[e];
    }
}

__global__ void gbound_kernel(const int* __restrict__ gids) {
    int g = threadIdx.x;
    if (g > NG) return;
    int lo = 0, hi = NN;
    while (lo < hi) {
        int mid = (lo + hi) >> 1;
        if (gids[mid] < g) lo = mid + 1; else hi = mid;
    }
    g_gstart[g] = lo;
}

// ------- fused edge kernel: one warp per NODE, all 8 heads at once -----------
__global__ __launch_bounds__(256) void fused_edge_kernel(const float* __restrict__ attn,
                                                         int do_pack)
{
    int n = blockIdx.x * 8 + (threadIdx.x >> 5);
    int lane = threadIdx.x & 31;
    if (n >= NN) return;
    const size_t rowoff = (size_t)n * HID + lane * 8;

    float fdv[8], av[8];
    {
        float4 t0 = *(const float4*)(g_fd + rowoff);
        float4 t1 = *(const float4*)(g_fd + rowoff + 4);
        fdv[0]=t0.x; fdv[1]=t0.y; fdv[2]=t0.z; fdv[3]=t0.w;
        fdv[4]=t1.x; fdv[5]=t1.y; fdv[6]=t1.z; fdv[7]=t1.w;
        float4 a0 = *(const float4*)(attn + lane * 8);
        float4 a1 = *(const float4*)(attn + lane * 8 + 4);
        av[0]=a0.x; av[1]=a0.y; av[2]=a0.z; av[3]=a0.w;
        av[4]=a1.x; av[5]=a1.y; av[6]=a1.z; av[7]=a1.w;
    }

    const int b  = g_base[n];
    const int e2 = g_base[n + 1];

    float m = -1e30f, sd = 0.f;
    float acc[8] = {0.f,0.f,0.f,0.f,0.f,0.f,0.f,0.f};

    for (int j = b; j < e2; j++) {
        int s = g_srcbyd[j];
        const float4* fp = (const float4*)(g_fs + (size_t)s * HID + lane * 8);
        float4 a0 = fp[0], a1 = fp[1];
        float fsv[8] = {a0.x,a0.y,a0.z,a0.w,a1.x,a1.y,a1.z,a1.w};
        float pp = 0.f;
        #pragma unroll
        for (int q = 0; q < 8; q++) {
            float v = fsv[q] + fdv[q];
            v = (v > 0.f) ? v : SLOPE * v;
            pp = fmaf(v, av[q], pp);
        }
        pp += __shfl_xor_sync(0xffffffffu, pp, 1);
        pp += __shfl_xor_sync(0xffffffffu, pp, 2);
        float nm = fmaxf(m, pp);
        float fac = __expf(m - nm);
        float w   = __expf(pp - nm);
        sd = sd * fac + w;
        #pragma unroll
        for (int q = 0; q < 8; q++) acc[q] = fmaf(acc[q], fac, w * fsv[q]);
        m = nm;
    }

    float inv = (sd > 0.f) ? 1.f / sd : 0.f;
    float hv[8];
    {
        float4 h0 = *(const float4*)(g_h + rowoff);
        float4 h1 = *(const float4*)(g_h + rowoff + 4);
        float hold[8] = {h0.x,h0.y,h0.z,h0.w,h1.x,h1.y,h1.z,h1.w};
        #pragma unroll
        for (int q = 0; q < 8; q++) hv[q] = fmaxf(fmaf(acc[q], inv, hold[q]), 0.f);
    }
    *(float4*)(g_h + rowoff)     = make_float4(hv[0], hv[1], hv[2], hv[3]);
    *(float4*)(g_h + rowoff + 4) = make_float4(hv[4], hv[5], hv[6], hv[7]);
    if (do_pack) {
        size_t pbase = rowoff >> 1;
        #pragma unroll
        for (int q = 0; q < 8; q += 2) {
            unsigned hi, lo;
            split_pack(hv[q], hv[q + 1], hi, lo);
            g_ah_hi[pbase + (q >> 1)] = hi;
            g_ah_lo[pbase + (q >> 1)] = lo;
        }
    }
}

// ---------------- fused pool + 3-layer classifier, one block per graph -------
__global__ __launch_bounds__(256) void poolfc_kernel(
    const float* __restrict__ Wc1, const float* __restrict__ bc1,
    const float* __restrict__ Wc2, const float* __restrict__ bc2,
    const float* __restrict__ Wc3, const float* __restrict__ bc3,
    float* __restrict__ out)
{
    __shared__ float sh[256];
    __shared__ float sx[256];
    int g = blockIdx.x;
    int c = threadIdx.x;
    int n0 = g_gstart[g], n1 = g_gstart[g + 1];
    float s = 0.f;
    for (int n = n0; n < n1; n++) s += g_h[(size_t)n * HID + c];
    sh[c] = s;
    __syncthreads();
    float a = bc1[c];
    #pragma unroll 8
    for (int k = 0; k < HID; k++) a = fmaf(sh[k], Wc1[k * HID + c], a);
    sx[c] = fmaxf(a, 0.f);
    __syncthreads();
    float b2 = 0.f;
    if (c < HID / 2) {
        b2 = bc2[c];
        #pragma unroll 8
        for (int k = 0; k < HID; k++) b2 = fmaf(sx[k], Wc2[k * (HID / 2) + c], b2);
        b2 = fmaxf(b2, 0.f);
    }
    __syncthreads();
    if (c < HID / 2) sh[c] = b2;
    __syncthreads();
    if (c < OUTDIM) {
        float o = bc3[c];
        for (int k = 0; k < HID / 2; k++) o = fmaf(sh[k], Wc3[k * OUTDIM + c], o);
        out[g * OUTDIM + c] = o;
    }
}

// ---------------- launch -------------------------------------------------------
extern "C" void kernel_launch(void* const* d_in, const int* in_sizes, int n_in,
                              void* d_out, int out_size)
{
    const float* feature   = (const float*)d_in[0];
    const float* W_in      = (const float*)d_in[1];
    const float* b_in      = (const float*)d_in[2];
    const float* W_src     = (const float*)d_in[3];
    const float* b_src     = (const float*)d_in[4];
    const float* W_dst     = (const float*)d_in[5];
    const float* b_dst     = (const float*)d_in[6];
    const float* attn      = (const float*)d_in[7];
    const float* Wc1       = (const float*)d_in[8];
    const float* bc1       = (const float*)d_in[9];
    const float* Wc2       = (const float*)d_in[10];
    const float* bc2       = (const float*)d_in[11];
    const float* Wc3       = (const float*)d_in[12];
    const float* bc3       = (const float*)d_in[13];
    const int*   src       = (const int*)d_in[14];
    const int*   dst       = (const int*)d_in[15];
    const int*   graph_ids = (const int*)d_in[16];
    float* out = (float*)d_out;

    float *p_h, *p_fs, *p_fd;
    unsigned *p_ah_hi, *p_ah_lo, *p_af_hi, *p_af_lo;
    unsigned *p_win_hi, *p_win_lo, *p_ws_hi, *p_ws_lo, *p_wd_hi, *p_wd_lo;
    cudaGetSymbolAddress((void**)&p_h,  g_h);
    cudaGetSymbolAddress((void**)&p_fs, g_fs);
    cudaGetSymbolAddress((void**)&p_fd, g_fd);
    cudaGetSymbolAddress((void**)&p_ah_hi, g_ah_hi);
    cudaGetSymbolAddress((void**)&p_ah_lo, g_ah_lo);
    cudaGetSymbolAddress((void**)&p_af_hi, g_af_hi);
    cudaGetSymbolAddress((void**)&p_af_lo, g_af_lo);
    cudaGetSymbolAddress((void**)&p_win_hi, g_win_hi);
    cudaGetSymbolAddress((void**)&p_win_lo, g_win_lo);
    cudaGetSymbolAddress((void**)&p_ws_hi, g_ws_hi);
    cudaGetSymbolAddress((void**)&p_ws_lo, g_ws_lo);
    cudaGetSymbolAddress((void**)&p_wd_hi, g_wd_hi);
    cudaGetSymbolAddress((void**)&p_wd_lo, g_wd_lo);

    cudaFuncSetAttribute(gemm_bf16x3_kernel,
                         cudaFuncAttributeMaxDynamicSharedMemorySize, GSMEM);

    // fork: CSR chain on a second stream, overlapped with pack + GEMM1
    cudaStream_t s2;
    cudaStreamCreateWithFlags(&s2, cudaStreamNonBlocking);
    cudaEvent_t evA, evB;
    cudaEventCreateWithFlags(&evA, cudaEventDisableTiming);
    cudaEventCreateWithFlags(&evB, cudaEventDisableTiming);
    cudaEventRecord(evA, 0);
    cudaStreamWaitEvent(s2, evA, 0);
    zero_cnt_kernel<<<(NN + 255) / 256, 256, 0, s2>>>();
    count_kernel<<<(NE + 255) / 256, 256, 0, s2>>>(dst);
    scan_kernel<<<1, 1024, 0, s2>>>();
    fill_kernel<<<(NE + 255) / 256, 256, 0, s2>>>(src, dst);
    gbound_kernel<<<1, 128, 0, s2>>>(graph_ids);
    cudaEventRecord(evB, s2);

    // main stream: pack, GEMM1
    const int NPACK = NN * K2IN + WIN_P + 2 * LAYERS * WL_P;
    pack_all_kernel<<<(NPACK + 255) / 256, 256>>>(W_in, W_src, W_dst, feature);

    const int MROWS = (NN + GBM - 1) / GBM;   // 313
    const int NB = HID / GBN;                 // 2
    dim3 grid1(NB, MROWS);
    dim3 grid2(2 * NB, MROWS);

    gemm_bf16x3_kernel<<<grid1, 256, GSMEM>>>(
        p_af_hi, p_af_lo, p_win_hi, p_win_lo, p_win_hi, p_win_lo,
        b_in, b_in, p_h, p_h, p_ah_hi, p_ah_lo,
        NN, K2IN, NB, 1);

    cudaStreamWaitEvent(0, evB, 0);

    const int fused_blocks = (NN + 7) / 8;
    for (int l = 0; l < LAYERS; l++) {
        const float* bs = b_src + (size_t)l * HID;
        const float* bd = b_dst + (size_t)l * HID;
        const float* al = attn + (size_t)l * HEADS * DH;

        gemm_bf16x3_kernel<<<grid2, 256, GSMEM>>>(
            p_ah_hi, p_ah_lo,
            p_ws_hi + (size_t)l * WL_P, p_ws_lo + (size_t)l * WL_P,
            p_wd_hi + (size_t)l * WL_P, p_wd_lo + (size_t)l * WL_P,
            bs, bd, p_fs, p_fd, (unsigned*)0, (unsigned*)0,
            NN, K2L, NB, 0);

        fused_edge_kernel<<<fused_blocks, 256>>>(al, (l + 1 < LAYERS) ? 1 : 0);
    }

    poolfc_kernel<<<NG, 256>>>(Wc1, bc1, Wc2, bc2, Wc3, bc3, out);
}

// round 12
// speedup vs baseline: 1.1232x; 1.0396x over previous
#include <cuda_runtime.h>
#include <cuda_bf16.h>
#include <math.h>

#define NN      20000
#define NE      320000
#define INDIM   128
#define HID     256
#define HEADS   8
#define DH      32
#define LAYERS  3
#define NG      64
#define OUTDIM  10
#define SLOPE   0.2f

#define K2IN  (INDIM / 2)
#define K2L   (HID / 2)
#define WIN_P (K2IN * HID)
#define WL_P  (K2L * HID)

// ---------------- scratch (device globals; no allocation allowed) ----------
__device__ float g_h[NN * HID];
__device__ float g_fs[NN * HID];
__device__ float g_fd[NN * HID];
__device__ unsigned g_ah_hi[NN * K2L];
__device__ unsigned g_ah_lo[NN * K2L];
__device__ unsigned g_af_hi[NN * K2IN];
__device__ unsigned g_af_lo[NN * K2IN];
__device__ unsigned g_win_hi[WIN_P], g_win_lo[WIN_P];
__device__ unsigned g_ws_hi[LAYERS * WL_P], g_ws_lo[LAYERS * WL_P];
__device__ unsigned g_wd_hi[LAYERS * WL_P], g_wd_lo[LAYERS * WL_P];
__device__ int g_cnt[NN];
__device__ int g_base[NN + 1];
__device__ int g_cur[NN];
__device__ int g_srcbyd[NE];
__device__ int g_gstart[NG + 1];

// ---------------- bf16 pack helpers -----------------------------------------
__device__ __forceinline__ unsigned pack_bf2(__nv_bfloat16 a, __nv_bfloat16 b) {
    return ((unsigned)__bfloat16_as_ushort(b) << 16) | (unsigned)__bfloat16_as_ushort(a);
}

__device__ __forceinline__ void split_pack(float x0, float x1, unsigned& hi, unsigned& lo) {
    __nv_bfloat16 h0 = __float2bfloat16_rn(x0);
    __nv_bfloat16 h1 = __float2bfloat16_rn(x1);
    __nv_bfloat16 l0 = __float2bfloat16_rn(x0 - __bfloat162float(h0));
    __nv_bfloat16 l1 = __float2bfloat16_rn(x1 - __bfloat162float(h1));
    hi = pack_bf2(h0, h1);
    lo = pack_bf2(l0, l1);
}

__device__ __forceinline__ void mma_bf16(float c[4], const unsigned a[4], const unsigned b[2]) {
    asm volatile(
        "mma.sync.aligned.m16n8k16.row.col.f32.bf16.bf16.f32 "
        "{%0,%1,%2,%3}, {%4,%5,%6,%7}, {%8,%9}, {%0,%1,%2,%3};"
        : "+f"(c[0]), "+f"(c[1]), "+f"(c[2]), "+f"(c[3])
        : "r"(a[0]), "r"(a[1]), "r"(a[2]), "r"(a[3]), "r"(b[0]), "r"(b[1]));
}

__device__ __forceinline__ void ldsm_x4(unsigned r[4], unsigned addr) {
    asm volatile("ldmatrix.sync.aligned.m8n8.x4.shared.b16 {%0,%1,%2,%3}, [%4];"
        : "=r"(r[0]), "=r"(r[1]), "=r"(r[2]), "=r"(r[3]) : "r"(addr));
}

__device__ __forceinline__ void cp_async16(unsigned saddr, const void* g, unsigned srcsz) {
    asm volatile("cp.async.cg.shared.global [%0], [%1], 16, %2;"
                 :: "r"(saddr), "l"(g), "r"(srcsz) : "memory");
}
#define CP_COMMIT() asm volatile("cp.async.commit_group;" ::: "memory")
#define CP_WAIT(n)  asm volatile("cp.async.wait_group %0;" :: "n"(n) : "memory")

// ---------------- pack everything in one launch -------------------------------
__global__ void pack_all_kernel(const float* __restrict__ W_in,
                                const float* __restrict__ W_src,
                                const float* __restrict__ W_dst,
                                const float* __restrict__ feature)
{
    int i = blockIdx.x * blockDim.x + threadIdx.x;
    const int NF = NN * K2IN;
    if (i < NF) {
        float2 v = ((const float2*)feature)[i];
        split_pack(v.x, v.y, g_af_hi[i], g_af_lo[i]);
        return;
    }
    int j = i - NF;
    if (j < WIN_P) {
        int k2 = j >> 8, n = j & 255;
        split_pack(W_in[(2 * k2) * HID + n], W_in[(2 * k2 + 1) * HID + n],
                   g_win_hi[j], g_win_lo[j]);
        return;
    }
    j -= WIN_P;
    if (j >= 2 * LAYERS * WL_P) return;
    int which = j / (LAYERS * WL_P);
    int rem = j - which * (LAYERS * WL_P);
    int l = rem / WL_P;
    int p = rem - l * WL_P;
    int k2 = p >> 8, n = p & 255;
    const float* W = (which ? W_dst : W_src) + (size_t)l * HID * HID;
    unsigned* hi = (which ? g_wd_hi : g_ws_hi) + (size_t)l * WL_P;
    unsigned* lo = (which ? g_wd_lo : g_ws_lo) + (size_t)l * WL_P;
    split_pack(W[(2 * k2) * HID + n], W[(2 * k2 + 1) * HID + n], hi[p], lo[p]);
}

// ------- bf16x3 mma.sync GEMM: 64x128 tile, cp.async 3-stage pipeline --------
// C[M,256] = A[M,K]@B[K,256] + bias. grid.x in [0,2*nb).
#define GBM 64
#define GBN 128
#define AST 20
#define BST 136
// per-stage layout (bytes): As_hi 0..5120, As_lo 5120..10240,
// Bs_hi 10240..18944, Bs_lo 18944..27648
#define STG   27648
#define GSMEM (3 * STG)           // 82944

__global__ __launch_bounds__(256) void gemm_bf16x3_kernel(
    const unsigned* __restrict__ Ahi, const unsigned* __restrict__ Alo,
    const unsigned* __restrict__ B1hi, const unsigned* __restrict__ B1lo,
    const unsigned* __restrict__ B2hi, const unsigned* __restrict__ B2lo,
    const float* __restrict__ bias1, const float* __restrict__ bias2,
    float* __restrict__ C1, float* __restrict__ C2,
    unsigned* __restrict__ Pho, unsigned* __restrict__ Plo,
    int M, int K2g, int nb, int do_pack)
{
    extern __shared__ __align__(16) unsigned char dsm[];
    const unsigned sbase = (unsigned)__cvta_generic_to_shared(dsm);

    int bx = blockIdx.x;
    int which = 0;
    if (bx >= nb) { which = 1; bx -= nb; }
    const unsigned* Bhi = which ? B2hi : B1hi;
    const unsigned* Blo = which ? B2lo : B1lo;
    const float* bias   = which ? bias2 : bias1;
    float* C            = which ? C2 : C1;

    const int tid  = threadIdx.x;
    const int wid  = tid >> 5;              // 0..7
    const int lane = tid & 31;
    const int wm   = (wid >> 2) * 32;       // 0,32
    const int wn   = (wid & 3) * 32;        // 0..96
    const int grp  = lane >> 2;
    const int tig  = lane & 3;
    const int row0 = blockIdx.y * GBM;
    const int col0 = bx * GBN;

    // loader mapping: A 64 rows x 16 pairs (1 x 16B / thread / array);
    // B 16 rows x 128 cols (2 x 16B / thread / array)
    const int arw = tid >> 2;
    const int asg = (tid & 3) * 4;
    const int brw = tid >> 5;
    const int bcc = (tid & 31) * 4;

    const int lrow = wm + (lane & 15);
    const int lcol = (lane >> 4) * 4;

    // A global row (clamped for cp.async src address validity)
    const bool a_ok = (row0 + arw) < M;
    const int arow_c = a_ok ? (row0 + arw) : (M - 1);
    const unsigned a_srcsz = a_ok ? 16u : 0u;
    // smem intra-stage offsets (bytes)
    const unsigned a_soff = (arw * AST + asg) * 4u;
    const unsigned b_soff0 = 10240u + (brw * BST + bcc) * 4u;
    const unsigned b_soff1 = 10240u + ((brw + 8) * BST + bcc) * 4u;

    #define ISSUE_TILE(t, s) do {                                             \
        int kb = (t) * 16;                                                    \
        unsigned sb = sbase + (unsigned)(s) * STG;                            \
        size_t ga = (size_t)arow_c * K2g + kb + asg;                          \
        cp_async16(sb + a_soff,         Ahi + ga, a_srcsz);                   \
        cp_async16(sb + 5120 + a_soff,  Alo + ga, a_srcsz);                   \
        size_t gb0 = (size_t)(kb + brw) * 256 + col0 + bcc;                   \
        size_t gb1 = (size_t)(kb + brw + 8) * 256 + col0 + bcc;               \
        cp_async16(sb + b_soff0,        Bhi + gb0, 16u);                      \
        cp_async16(sb + 8704 + b_soff0, Blo + gb0, 16u);                      \
        cp_async16(sb + b_soff1,        Bhi + gb1, 16u);                      \
        cp_async16(sb + 8704 + b_soff1, Blo + gb1, 16u);                      \
    } while (0)

    float c[2][4][4];
    #pragma unroll
    for (int i = 0; i < 2; i++)
        #pragma unroll
        for (int j = 0; j < 4; j++)
            #pragma unroll
            for (int k = 0; k < 4; k++) c[i][j][k] = 0.f;

    const int nk = K2g >> 4;   // k-tiles of 32 k
    ISSUE_TILE(0, 0);
    CP_COMMIT();
    if (nk > 1) { ISSUE_TILE(1, 1); CP_COMMIT(); }

    int s = 0;
    for (int t = 0; t < nk; t++) {
        if (t + 1 < nk) CP_WAIT(1); else CP_WAIT(0);
        __syncthreads();

        const unsigned stg = sbase + (unsigned)s * STG;
        const unsigned* Bsh = (const unsigned*)(dsm + s * STG + 10240);
        const unsigned* Bsl = (const unsigned*)(dsm + s * STG + 18944);

        #pragma unroll
        for (int kk = 0; kk < 2; kk++) {
            unsigned ah[2][4], al[2][4], bh[4][2], bl[4][2];
            #pragma unroll
            for (int mt = 0; mt < 2; mt++) {
                unsigned off = ((unsigned)(lrow + mt * 16) * AST + kk * 8 + lcol) * 4u;
                ldsm_x4(ah[mt], stg + off);
                ldsm_x4(al[mt], stg + 5120 + off);
            }
            #pragma unroll
            for (int nt = 0; nt < 4; nt++) {
                int cn = wn + nt * 8 + grp;
                int r0 = (kk * 8 + tig) * BST;
                bh[nt][0] = Bsh[r0 + cn];      bh[nt][1] = Bsh[r0 + 4 * BST + cn];
                bl[nt][0] = Bsl[r0 + cn];      bl[nt][1] = Bsl[r0 + 4 * BST + cn];
            }
            #pragma unroll
            for (int mt = 0; mt < 2; mt++)
                #pragma unroll
                for (int nt = 0; nt < 4; nt++) {
                    mma_bf16(c[mt][nt], ah[mt], bl[nt]);
                    mma_bf16(c[mt][nt], al[mt], bh[nt]);
                    mma_bf16(c[mt][nt], ah[mt], bh[nt]);
                }
        }

        if (t + 2 < nk) {
            int s2i = s + 2; if (s2i >= 3) s2i -= 3;
            ISSUE_TILE(t + 2, s2i);
            CP_COMMIT();
        }
        s = (s + 1 == 3) ? 0 : s + 1;
    }

    #pragma unroll
    for (int nt = 0; nt < 4; nt++) {
        int cc = col0 + wn + nt * 8 + 2 * tig;
        float b0 = bias[cc], b1 = bias[cc + 1];
        #pragma unroll
        for (int mt = 0; mt < 2; mt++) {
            int r0 = row0 + wm + mt * 16 + grp;
            if (r0 < M) {
                float v0 = c[mt][nt][0] + b0, v1 = c[mt][nt][1] + b1;
                *(float2*)(C + (size_t)r0 * HID + cc) = make_float2(v0, v1);
                if (do_pack && which == 0) {
                    unsigned hi, lo;
                    split_pack(v0, v1, hi, lo);
                    size_t pi = ((size_t)r0 * HID + cc) >> 1;
                    Pho[pi] = hi; Plo[pi] = lo;
                }
            }
            int r1 = r0 + 8;
            if (r1 < M) {
                float v0 = c[mt][nt][2] + b0, v1 = c[mt][nt][3] + b1;
                *(float2*)(C + (size_t)r1 * HID + cc) = make_float2(v0, v1);
                if (do_pack && which == 0) {
                    unsigned hi, lo;
                    split_pack(v0, v1, hi, lo);
                    size_t pi = ((size_t)r1 * HID + cc) >> 1;
                    Pho[pi] = hi; Plo[pi] = lo;
                }
            }
        }
    }
    #undef ISSUE_TILE
}

// ---------------- CSR build (second stream) ----------------------------------
__global__ void zero_cnt_kernel() {
    int i = blockIdx.x * blockDim.x + threadIdx.x;
    if (i < NN) g_cnt[i] = 0;
}

__global__ void count_kernel(const int* __restrict__ dst) {
    int e = blockIdx.x * blockDim.x + threadIdx.x;
    if (e < NE) atomicAdd(&g_cnt[dst[e]], 1);
}

__global__ __launch_bounds__(1024) void scan_kernel() {
    __shared__ int s[1024];
    int t = threadIdx.x;
    int lo = t * 20;
    int hi = lo + 20; if (hi > NN) hi = NN;
    int sum = 0;
    for (int i = lo; i < hi; i++) sum += g_cnt[i];
    s[t] = sum;
    __syncthreads();
    for (int off = 1; off < 1024; off <<= 1) {
        int v = (t >= off) ? s[t - off] : 0;
        __syncthreads();
        s[t] += v;
        __syncthreads();
    }
    int run = s[t] - sum;
    for (int i = lo; i < hi; i++) {
        g_base[i] = run;
        g_cur[i] = run;
        run += g_cnt[i];
    }
    if (t == 0) g_base[NN] = NE;
}

__global__ void fill_kernel(const int* __restrict__ src, const int* __restrict__ dst) {
    int e = blockIdx.x * blockDim.x + threadIdx.x;
    if (e < NE) {
        int p = atomicAdd(&g_cur[dst[e]], 1);
        g_srcbyd[p] = src[e];
    }
}

__global__ void gbound_kernel(const int* __restrict__ gids) {
    int g = threadIdx.x;
    if (g > NG) return;
    int lo = 0, hi = NN;
    while (lo < hi) {
        int mid = (lo + hi) >> 1;
        if (gids[mid] < g) lo = mid + 1; else hi = mid;
    }
    g_gstart[g] = lo;
}

// ------- fused edge kernel: one warp per NODE, all 8 heads at once -----------
__global__ __launch_bounds__(256) void fused_edge_kernel(const float* __restrict__ attn,
                                                         int do_pack)
{
    int n = blockIdx.x * 8 + (threadIdx.x >> 5);
    int lane = threadIdx.x & 31;
    if (n >= NN) return;
    const size_t rowoff = (size_t)n * HID + lane * 8;

    float fdv[8], av[8];
    {
        float4 t0 = *(const float4*)(g_fd + rowoff);
        float4 t1 = *(const float4*)(g_fd + rowoff + 4);
        fdv[0]=t0.x; fdv[1]=t0.y; fdv[2]=t0.z; fdv[3]=t0.w;
        fdv[4]=t1.x; fdv[5]=t1.y; fdv[6]=t1.z; fdv[7]=t1.w;
        float4 a0 = *(const float4*)(attn + lane * 8);
        float4 a1 = *(const float4*)(attn + lane * 8 + 4);
        av[0]=a0.x; av[1]=a0.y; av[2]=a0.z; av[3]=a0.w;
        av[4]=a1.x; av[5]=a1.y; av[6]=a1.z; av[7]=a1.w;
    }

    const int b  = g_base[n];
    const int e2 = g_base[n + 1];

    float m = -1e30f, sd = 0.f;
    float acc[8] = {0.f,0.f,0.f,0.f,0.f,0.f,0.f,0.f};

    for (int j = b; j < e2; j++) {
        int s = g_srcbyd[j];
        const float4* fp = (const float4*)(g_fs + (size_t)s * HID + lane * 8);
        float4 a0 = fp[0], a1 = fp[1];
        float fsv[8] = {a0.x,a0.y,a0.z,a0.w,a1.x,a1.y,a1.z,a1.w};
        float pp = 0.f;
        #pragma unroll
        for (int q = 0; q < 8; q++) {
            float v = fsv[q] + fdv[q];
            v = (v > 0.f) ? v : SLOPE * v;
            pp = fmaf(v, av[q], pp);
        }
        pp += __shfl_xor_sync(0xffffffffu, pp, 1);
        pp += __shfl_xor_sync(0xffffffffu, pp, 2);
        float nm = fmaxf(m, pp);
        float fac = __expf(m - nm);
        float w   = __expf(pp - nm);
        sd = sd * fac + w;
        #pragma unroll
        for (int q = 0; q < 8; q++) acc[q] = fmaf(acc[q], fac, w * fsv[q]);
        m = nm;
    }

    float inv = (sd > 0.f) ? 1.f / sd : 0.f;
    float hv[8];
    {
        float4 h0 = *(const float4*)(g_h + rowoff);
        float4 h1 = *(const float4*)(g_h + rowoff + 4);
        float hold[8] = {h0.x,h0.y,h0.z,h0.w,h1.x,h1.y,h1.z,h1.w};
        #pragma unroll
        for (int q = 0; q < 8; q++) hv[q] = fmaxf(fmaf(acc[q], inv, hold[q]), 0.f);
    }
    *(float4*)(g_h + rowoff)     = make_float4(hv[0], hv[1], hv[2], hv[3]);
    *(float4*)(g_h + rowoff + 4) = make_float4(hv[4], hv[5], hv[6], hv[7]);
    if (do_pack) {
        size_t pbase = rowoff >> 1;
        #pragma unroll
        for (int q = 0; q < 8; q += 2) {
            unsigned hi, lo;
            split_pack(hv[q], hv[q + 1], hi, lo);
            g_ah_hi[pbase + (q >> 1)] = hi;
            g_ah_lo[pbase + (q >> 1)] = lo;
        }
    }
}

// ---------------- fused pool + 3-layer classifier, one block per graph -------
__global__ __launch_bounds__(256) void poolfc_kernel(
    const float* __restrict__ Wc1, const float* __restrict__ bc1,
    const float* __restrict__ Wc2, const float* __restrict__ bc2,
    const float* __restrict__ Wc3, const float* __restrict__ bc3,
    float* __restrict__ out)
{
    __shared__ float sh[256];
    __shared__ float sx[256];
    int g = blockIdx.x;
    int c = threadIdx.x;
    int n0 = g_gstart[g], n1 = g_gstart[g + 1];
    float s = 0.f;
    for (int n = n0; n < n1; n++) s += g_h[(size_t)n * HID + c];
    sh[c] = s;
    __syncthreads();
    float a = bc1[c];
    #pragma unroll 8
    for (int k = 0; k < HID; k++) a = fmaf(sh[k], Wc1[k * HID + c], a);
    sx[c] = fmaxf(a, 0.f);
    __syncthreads();
    float b2 = 0.f;
    if (c < HID / 2) {
        b2 = bc2[c];
        #pragma unroll 8
        for (int k = 0; k < HID; k++) b2 = fmaf(sx[k], Wc2[k * (HID / 2) + c], b2);
        b2 = fmaxf(b2, 0.f);
    }
    __syncthreads();
    if (c < HID / 2) sh[c] = b2;
    __syncthreads();
    if (c < OUTDIM) {
        float o = bc3[c];
        for (int k = 0; k < HID / 2; k++) o = fmaf(sh[k], Wc3[k * OUTDIM + c], o);
        out[g * OUTDIM + c] = o;
    }
}

// ---------------- launch -------------------------------------------------------
extern "C" void kernel_launch(void* const* d_in, const int* in_sizes, int n_in,
                              void* d_out, int out_size)
{
    const float* feature   = (const float*)d_in[0];
    const float* W_in      = (const float*)d_in[1];
    const float* b_in      = (const float*)d_in[2];
    const float* W_src     = (const float*)d_in[3];
    const float* b_src     = (const float*)d_in[4];
    const float* W_dst     = (const float*)d_in[5];
    const float* b_dst     = (const float*)d_in[6];
    const float* attn      = (const float*)d_in[7];
    const float* Wc1       = (const float*)d_in[8];
    const float* bc1       = (const float*)d_in[9];
    const float* Wc2       = (const float*)d_in[10];
    const float* bc2       = (const float*)d_in[11];
    const float* Wc3       = (const float*)d_in[12];
    const float* bc3       = (const float*)d_in[13];
    const int*   src       = (const int*)d_in[14];
    const int*   dst       = (const int*)d_in[15];
    const int*   graph_ids = (const int*)d_in[16];
    float* out = (float*)d_out;

    float *p_h, *p_fs, *p_fd;
    unsigned *p_ah_hi, *p_ah_lo, *p_af_hi, *p_af_lo;
    unsigned *p_win_hi, *p_win_lo, *p_ws_hi, *p_ws_lo, *p_wd_hi, *p_wd_lo;
    cudaGetSymbolAddress((void**)&p_h,  g_h);
    cudaGetSymbolAddress((void**)&p_fs, g_fs);
    cudaGetSymbolAddress((void**)&p_fd, g_fd);
    cudaGetSymbolAddress((void**)&p_ah_hi, g_ah_hi);
    cudaGetSymbolAddress((void**)&p_ah_lo, g_ah_lo);
    cudaGetSymbolAddress((void**)&p_af_hi, g_af_hi);
    cudaGetSymbolAddress((void**)&p_af_lo, g_af_lo);
    cudaGetSymbolAddress((void**)&p_win_hi, g_win_hi);
    cudaGetSymbolAddress((void**)&p_win_lo, g_win_lo);
    cudaGetSymbolAddress((void**)&p_ws_hi, g_ws_hi);
    cudaGetSymbolAddress((void**)&p_ws_lo, g_ws_lo);
    cudaGetSymbolAddress((void**)&p_wd_hi, g_wd_hi);
    cudaGetSymbolAddress((void**)&p_wd_lo, g_wd_lo);

    cudaFuncSetAttribute(gemm_bf16x3_kernel,
                         cudaFuncAttributeMaxDynamicSharedMemorySize, GSMEM);

    cudaStream_t s2;
    cudaStreamCreateWithFlags(&s2, cudaStreamNonBlocking);
    cudaEvent_t evA, evB;
    cudaEventCreateWithFlags(&evA, cudaEventDisableTiming);
    cudaEventCreateWithFlags(&evB, cudaEventDisableTiming);

    // launch #1: pack (main)
    const int NPACK = NN * K2IN + WIN_P + 2 * LAYERS * WL_P;
    cudaEventRecord(evA, 0);
    pack_all_kernel<<<(NPACK + 255) / 256, 256>>>(W_in, W_src, W_dst, feature);

    // launches #2-5: CSR chain (stream 2)
    cudaStreamWaitEvent(s2, evA, 0);
    zero_cnt_kernel<<<(NN + 255) / 256, 256, 0, s2>>>();
    count_kernel<<<(NE + 255) / 256, 256, 0, s2>>>(dst);
    scan_kernel<<<1, 1024, 0, s2>>>();
    fill_kernel<<<(NE + 255) / 256, 256, 0, s2>>>(src, dst);

    const int MROWS = (NN + GBM - 1) / GBM;   // 313
    const int NB = HID / GBN;                 // 2
    dim3 grid1(NB, MROWS);
    dim3 grid2(2 * NB, MROWS);

    // launch #6: input GEMM (ncu -s 5 -c 1 capture target)
    gemm_bf16x3_kernel<<<grid1, 256, GSMEM>>>(
        p_af_hi, p_af_lo, p_win_hi, p_win_lo, p_win_hi, p_win_lo,
        b_in, b_in, p_h, p_h, p_ah_hi, p_ah_lo,
        NN, K2IN, NB, 1);

    gbound_kernel<<<1, 128, 0, s2>>>(graph_ids);
    cudaEventRecord(evB, s2);
    cudaStreamWaitEvent(0, evB, 0);

    const int fused_blocks = (NN + 7) / 8;
    for (int l = 0; l < LAYERS; l++) {
        const float* bs = b_src + (size_t)l * HID;
        const float* bd = b_dst + (size_t)l * HID;
        const float* al = attn + (size_t)l * HEADS * DH;

        gemm_bf16x3_kernel<<<grid2, 256, GSMEM>>>(
            p_ah_hi, p_ah_lo,
            p_ws_hi + (size_t)l * WL_P, p_ws_lo + (size_t)l * WL_P,
            p_wd_hi + (size_t)l * WL_P, p_wd_lo + (size_t)l * WL_P,
            bs, bd, p_fs, p_fd, (unsigned*)0, (unsigned*)0,
            NN, K2L, NB, 0);

        fused_edge_kernel<<<fused_blocks, 256>>>(al, (l + 1 < LAYERS) ? 1 : 0);
    }

    poolfc_kernel<<<NG, 256>>>(Wc1, bc1, Wc2, bc2, Wc3, bc3, out);
}